// round 5
// baseline (speedup 1.0000x reference)
#include <cuda_runtime.h>
#include <cuda_bf16.h>

// Problem constants
#define BB    8
#define NN    4096
#define WROW  128          // 4096/32 bitmask words per row
#define ROWS  (BB*NN)      // 32768
#define INDIM 16420
#define HID   128
#define NACT  16
#define CK    514          // fc1 split-K chunk (32*514 >= 16420)
#define NQ    8            // column eighths per row in agg (512 cols each)

// ---------------- scratch (static __device__, no allocations) ----------------
__device__ unsigned g_bits[(size_t)ROWS * WROW];   // 16 MB packed adjacency (with self loops)
__device__ float    g_dinv[ROWS];
__device__ float4   g_v [ROWS];                    // dinv * (x @ W1)
__device__ float4   g_v2[ROWS];                    // dinv * (h @ W2)
__device__ float4   g_h2[ROWS];                    // final GCN output h (layer2)
__device__ float4   g_pa[NQ * ROWS];               // layer1 partial sums (col eighths)
__device__ float4   g_pb[NQ * ROWS];               // layer2 partial sums
__device__ float    g_zacc[BB * HID];

// ---------------- K1: adj -> bitmask + dinv + v1 + zacc init ----------------
__global__ void __launch_bounds__(256) prep_kernel(
    const int* __restrict__ adj, const float* __restrict__ x,
    const float* __restrict__ W1, const float* __restrict__ fcb1)
{
    int row = blockIdx.x;                 // 0..32767
    int i   = row & (NN - 1);
    int t   = threadIdx.x;
    int lane = t & 31;

    // fused zacc init (first 8 blocks)
    if (row < BB && t < HID) g_zacc[row * HID + t] = fcb1[t];

    const int4* arow = (const int4*)(adj + ((size_t)row << 12));
    unsigned*   brow = g_bits + ((size_t)row << 7);

    unsigned cnt = 0;
#pragma unroll
    for (int it = 0; it < 4; ++it) {
        int j0 = it * 1024 + t * 4;
        int4 v = arow[it * 256 + t];
        unsigned nib = (unsigned)((v.x != 0) | ((v.y != 0) << 1) |
                                  ((v.z != 0) << 2) | ((v.w != 0) << 3));
        unsigned dio = (unsigned)(i - j0);
        if (dio < 4u) nib |= 1u << dio;   // force self-loop (A = max(A, I))
        unsigned w = nib << ((lane & 7) * 4);
        w |= __shfl_xor_sync(0xffffffffu, w, 1);
        w |= __shfl_xor_sync(0xffffffffu, w, 2);
        w |= __shfl_xor_sync(0xffffffffu, w, 4);
        if ((lane & 7) == 0) {
            brow[j0 >> 5] = w;
            cnt += __popc(w);
        }
    }
    // block reduce degree
    cnt += __shfl_down_sync(0xffffffffu, cnt, 16);
    cnt += __shfl_down_sync(0xffffffffu, cnt, 8);
    cnt += __shfl_down_sync(0xffffffffu, cnt, 4);
    cnt += __shfl_down_sync(0xffffffffu, cnt, 2);
    cnt += __shfl_down_sync(0xffffffffu, cnt, 1);
    __shared__ unsigned scnt[8];
    if (lane == 0) scnt[t >> 5] = cnt;
    __syncthreads();
    if (t == 0) {
        unsigned deg = 0;
#pragma unroll
        for (int w = 0; w < 8; ++w) deg += scnt[w];
        float d = rsqrtf((float)deg);
        g_dinv[row] = d;
        // fused v1: v = dinv * (x @ W1)
        float x0 = x[row*3], x1 = x[row*3+1], x2 = x[row*3+2];
        float u0 = x0*W1[0] + x1*W1[3] + x2*W1[6];
        float u1 = x0*W1[1] + x1*W1[4] + x2*W1[7];
        float u2 = x0*W1[2] + x1*W1[5] + x2*W1[8];
        g_v[row] = make_float4(d*u0, d*u1, d*u2, 0.f);
    }
}

// ---------------- nibble-LUT masked aggregation ----------------
// Per 4 columns: extract nibble, one broadcast-ish LDS.128 of the precomputed
// partial sum (x,y,z,z), two packed add.rn.f32x2. No predicates, no per-bit work.

#define NIBACC(AXY, AZZ, ADDR)                                                \
    {                                                                         \
        unsigned long long exy_, ezz_;                                        \
        asm volatile("ld.shared.v2.b64 {%0,%1}, [%2];"                        \
                     : "=l"(exy_), "=l"(ezz_) : "r"(ADDR));                   \
        asm volatile("add.rn.f32x2 %0, %0, %1;" : "+l"(AXY) : "l"(exy_));     \
        asm volatile("add.rn.f32x2 %0, %0, %1;" : "+l"(AZZ) : "l"(ezz_));     \
    }

// process one 32-bit word = 8 nibbles; word's LUT region is 8 groups * 256B
__device__ __forceinline__ void word8(
    unsigned w, unsigned base,
    unsigned long long& a0, unsigned long long& z0,
    unsigned long long& a1, unsigned long long& z1)
{
#pragma unroll
    for (int n = 0; n < 8; n += 2) {
        unsigned nib0 = (w >> (4 * n)) & 0xFu;
        unsigned nib1 = (w >> (4 * n + 4)) & 0xFu;
        NIBACC(a0, z0, base + n * 256 + nib0 * 16);
        NIBACC(a1, z1, base + n * 256 + 256 + nib1 * 16);
    }
}

// grid = 2048 blocks: (b in 8) x (tile in 32) x (eighth in 8); 128 threads = 128 rows
template<int L>
__global__ void __launch_bounds__(128) agg_kernel()
{
    __shared__ float4 lut[128 * 16];   // 32 KB: 128 groups x 16 entries (x,y,z,z)

    const float4* vin  = (L == 0) ? g_v  : g_v2;
    float4*       part = (L == 0) ? g_pa : g_pb;

    int bx   = blockIdx.x;
    int b    = bx >> 8;
    int tile = (bx >> 3) & 31;
    int q    = bx & 7;
    int t    = threadIdx.x;
    int row  = b * NN + tile * 128 + t;

    // load this row's 16 bitmask words (columns [q*512, q*512+512))
    const uint4* gw = (const uint4*)(g_bits + (size_t)row * WROW + q * 16);
    uint4 w0 = gw[0], w1 = gw[1], w2 = gw[2], w3 = gw[3];

    // build LUT: thread t = group t, columns q*512 + 4t .. 4t+3
    {
        const float4* vg = vin + b * NN + q * 512 + 4 * t;
        float4 v0 = vg[0], v1 = vg[1], v2 = vg[2], v3 = vg[3];
        float4 s[16];
        s[0]  = make_float4(0.f, 0.f, 0.f, 0.f);
        s[1]  = v0;
        s[2]  = v1;
        s[3]  = make_float4(v0.x+v1.x, v0.y+v1.y, v0.z+v1.z, 0.f);
        s[4]  = v2;
        s[5]  = make_float4(v0.x+v2.x, v0.y+v2.y, v0.z+v2.z, 0.f);
        s[6]  = make_float4(v1.x+v2.x, v1.y+v2.y, v1.z+v2.z, 0.f);
        s[7]  = make_float4(s[3].x+v2.x, s[3].y+v2.y, s[3].z+v2.z, 0.f);
        s[8]  = v3;
        s[9]  = make_float4(v0.x+v3.x, v0.y+v3.y, v0.z+v3.z, 0.f);
        s[10] = make_float4(v1.x+v3.x, v1.y+v3.y, v1.z+v3.z, 0.f);
        s[11] = make_float4(s[3].x+v3.x, s[3].y+v3.y, s[3].z+v3.z, 0.f);
        s[12] = make_float4(v2.x+v3.x, v2.y+v3.y, v2.z+v3.z, 0.f);
        s[13] = make_float4(s[5].x+v3.x, s[5].y+v3.y, s[5].z+v3.z, 0.f);
        s[14] = make_float4(s[6].x+v3.x, s[6].y+v3.y, s[6].z+v3.z, 0.f);
        s[15] = make_float4(s[7].x+v3.x, s[7].y+v3.y, s[7].z+v3.z, 0.f);
        float4* e = &lut[t * 16];
#pragma unroll
        for (int i = 0; i < 16; ++i)
            e[i] = make_float4(s[i].x, s[i].y, s[i].z, s[i].z);  // (x,y,z,z)
    }
    __syncthreads();

    unsigned sva = (unsigned)__cvta_generic_to_shared(lut);

    unsigned long long a0 = 0ull, a1 = 0ull, z0 = 0ull, z1 = 0ull;

    // 16 words; word k's LUT base = sva + k*2048 (8 groups * 256B per word)
    word8(w0.x, sva +  0 * 2048, a0, z0, a1, z1);
    word8(w0.y, sva +  1 * 2048, a0, z0, a1, z1);
    word8(w0.z, sva +  2 * 2048, a0, z0, a1, z1);
    word8(w0.w, sva +  3 * 2048, a0, z0, a1, z1);
    word8(w1.x, sva +  4 * 2048, a0, z0, a1, z1);
    word8(w1.y, sva +  5 * 2048, a0, z0, a1, z1);
    word8(w1.z, sva +  6 * 2048, a0, z0, a1, z1);
    word8(w1.w, sva +  7 * 2048, a0, z0, a1, z1);
    word8(w2.x, sva +  8 * 2048, a0, z0, a1, z1);
    word8(w2.y, sva +  9 * 2048, a0, z0, a1, z1);
    word8(w2.z, sva + 10 * 2048, a0, z0, a1, z1);
    word8(w2.w, sva + 11 * 2048, a0, z0, a1, z1);
    word8(w3.x, sva + 12 * 2048, a0, z0, a1, z1);
    word8(w3.y, sva + 13 * 2048, a0, z0, a1, z1);
    word8(w3.z, sva + 14 * 2048, a0, z0, a1, z1);
    word8(w3.w, sva + 15 * 2048, a0, z0, a1, z1);

    unsigned long long axy, azz;
    asm volatile("add.rn.f32x2 %0, %1, %2;" : "=l"(axy) : "l"(a0), "l"(a1));
    asm volatile("add.rn.f32x2 %0, %1, %2;" : "=l"(azz) : "l"(z0), "l"(z1));
    float ax, ay, az, dum;
    asm volatile("mov.b64 {%0, %1}, %2;" : "=f"(ax), "=f"(ay) : "l"(axy));
    asm volatile("mov.b64 {%0, %1}, %2;" : "=f"(az), "=f"(dum) : "l"(azz));

    part[q * ROWS + row] = make_float4(ax, ay, az, 0.f);
}

// ---------------- combine layer1 partials, relu, v2 = dinv * (h @ W2) ----------------
__global__ void v2_kernel(const float* __restrict__ W2, const float* __restrict__ b1)
{
    int id = blockIdx.x * blockDim.x + threadIdx.x;
    if (id >= ROWS) return;
    float sx = 0.f, sy = 0.f, sz = 0.f;
#pragma unroll
    for (int qq = 0; qq < NQ; ++qq) {
        float4 p = g_pa[qq * ROWS + id];
        sx += p.x; sy += p.y; sz += p.z;
    }
    float d = g_dinv[id];
    float h0 = fmaxf(d * sx + b1[0], 0.f);
    float h1 = fmaxf(d * sy + b1[1], 0.f);
    float h2 = fmaxf(d * sz + b1[2], 0.f);
    float u0 = h0*W2[0] + h1*W2[3] + h2*W2[6];
    float u1 = h0*W2[1] + h1*W2[4] + h2*W2[7];
    float u2 = h0*W2[2] + h1*W2[5] + h2*W2[8];
    g_v2[id] = make_float4(d*u0, d*u1, d*u2, 0.f);
}

// ---------------- combine layer2 partials -> final GCN h ----------------
__global__ void combine2_kernel(const float* __restrict__ b2)
{
    int id = blockIdx.x * blockDim.x + threadIdx.x;
    if (id >= ROWS) return;
    float sx = 0.f, sy = 0.f, sz = 0.f;
#pragma unroll
    for (int qq = 0; qq < NQ; ++qq) {
        float4 p = g_pb[qq * ROWS + id];
        sx += p.x; sy += p.y; sz += p.z;
    }
    float d = g_dinv[id];
    g_h2[id] = make_float4(d * sx + b2[0], d * sy + b2[1], d * sz + b2[2], 0.f);
}

// ---------------- fc1 split-K, z built on the fly, atomic accumulate ----------------
__global__ void __launch_bounds__(128) fc1_kernel(
    const float* __restrict__ idxin, const float* __restrict__ y,
    const float* __restrict__ fcW1)
{
    __shared__ float zc[CK];
    int bx = blockIdx.x;
    int b  = bx >> 5;
    int s  = bx & 31;
    int k0 = s * CK;
    int klen = min(CK, INDIM - k0);
    int t = threadIdx.x;

    for (int kk = t; kk < klen; kk += 128) {
        int k = k0 + kk;
        float z;
        if (k < NN) {
            z = idxin[b * NN + k];
        } else if (k < NN + 3 * NN) {
            int g = k - NN;
            int i = g / 3;
            int f = g - i * 3;
            z = ((const float*)&g_h2[b * NN + i])[f];
        } else {
            z = y[b * 36 + (k - (NN + 3 * NN))];
        }
        zc[kk] = z;
    }
    __syncthreads();

    float acc = 0.f;
    const float* wcol = fcW1 + (size_t)k0 * HID + t;
    int kk = 0;
    for (; kk + 4 <= klen; kk += 4) {
        acc += zc[kk+0] * wcol[(size_t)(kk+0) * HID];
        acc += zc[kk+1] * wcol[(size_t)(kk+1) * HID];
        acc += zc[kk+2] * wcol[(size_t)(kk+2) * HID];
        acc += zc[kk+3] * wcol[(size_t)(kk+3) * HID];
    }
    for (; kk < klen; ++kk)
        acc += zc[kk] * wcol[(size_t)kk * HID];

    atomicAdd(&g_zacc[b * HID + t], acc);
}

// ---------------- relu + fc2 ----------------
__global__ void __launch_bounds__(128) fin_kernel(
    const float* __restrict__ fcW2, const float* __restrict__ fcb2, float* __restrict__ out)
{
    __shared__ float sm[HID];
    int b = blockIdx.x, t = threadIdx.x;
    sm[t] = fmaxf(g_zacc[b * HID + t], 0.f);
    __syncthreads();
    if (t < NACT) {
        float o = fcb2[t];
#pragma unroll 8
        for (int h = 0; h < HID; ++h)
            o += sm[h] * fcW2[h * NACT + t];
        out[b * NACT + t] = o;
    }
}

// ---------------- launch ----------------
extern "C" void kernel_launch(void* const* d_in, const int* in_sizes, int n_in,
                              void* d_out, int out_size)
{
    const float* idxin = (const float*)d_in[0];   // [8,4096]
    const float* x     = (const float*)d_in[1];   // [8,4096,3]
    const float* y     = (const float*)d_in[2];   // [8,12,3]
    const int*   adj   = (const int*)  d_in[3];   // [8,4096,4096]
    const float* W1    = (const float*)d_in[4];
    const float* b1    = (const float*)d_in[5];
    const float* W2    = (const float*)d_in[6];
    const float* b2    = (const float*)d_in[7];
    const float* fcW1  = (const float*)d_in[8];
    const float* fcb1  = (const float*)d_in[9];
    const float* fcW2  = (const float*)d_in[10];
    const float* fcb2  = (const float*)d_in[11];
    float* out = (float*)d_out;

    prep_kernel<<<ROWS, 256>>>(adj, x, W1, fcb1);
    agg_kernel<0><<<2048, 128>>>();
    v2_kernel<<<ROWS / 256, 256>>>(W2, b1);
    agg_kernel<1><<<2048, 128>>>();
    combine2_kernel<<<ROWS / 256, 256>>>(b2);
    fc1_kernel<<<BB * 32, 128>>>(idxin, y, fcW1);
    fin_kernel<<<BB, 128>>>(fcW2, fcb2, out);
}